// round 12
// baseline (speedup 1.0000x reference)
#include <cuda_runtime.h>
#include <math.h>

// ---------------- problem constants ----------------
#define B32    32
#define TENC   256
#define TDEC   512
#define NMELS  80
#define EDIM   512
#define PRE    256
#define HID    1024
#define ATT    128
#define LOCF   32
#define LOCK   31
#define KA     1792           // PRE + EDIM + HID  (x | ctx | ah)
#define KD     2560           // HID + EDIM + HID  (ah | ctx | dh)
#define R4     4096
#define SPLT   4
#define NBLK   128
#define NTHR   256

#define MEL_SZ    (B32*NMELS*TDEC)
#define GATE_OFF  MEL_SZ
#define ALIGN_OFF (MEL_SZ + B32*TDEC)

// ---------------- static device buffers ----------------
__device__ float g_WaT[KA*R4];       // [k][r]
__device__ float g_WdT[KD*R4];       // [k][r]
__device__ float g_keys[B32*TENC*ATT];
__device__ float g_X[TDEC*B32*PRE];  // precomputed prenet outputs
__device__ float g_zpA[SPLT*B32*R4]; // split-K partials (attention LSTM)
__device__ float g_zpD[SPLT*B32*R4]; // split-K partials (decoder LSTM)
__device__ float g_Wqt[HID*ATT];
__device__ float g_Wmt[EDIM*ATT];
__device__ float g_Wp1t[NMELS*PRE];
__device__ float g_Wp2t[PRE*PRE];
__device__ float g_Wldt[LOCF*ATT];
__device__ float g_ba[R4];
__device__ float g_bd[R4];
__device__ float g_cat_a[B32*KA];    // [x | ctx | ah]
__device__ float g_cat_d[B32*KD];    // [ah | ctx | dh]
__device__ float g_ac[B32*HID];
__device__ float g_dc[B32*HID];
__device__ float g_aw[B32*TENC];
__device__ float g_awc[B32*TENC];
__device__ float g_q[B32*ATT];
__device__ float g_e[B32*TENC];

// grid barrier state (monotone epoch; works across graph replays without reset)
__device__ unsigned g_barcnt = 0;
__device__ volatile unsigned g_epoch = 0;

__device__ __forceinline__ float sigm(float x) { return 1.0f / (1.0f + expf(-x)); }
__device__ __forceinline__ unsigned rotl(unsigned x, int d) { return (x << d) | (x >> (32 - d)); }

__device__ __forceinline__ void gsync() {
    __syncthreads();
    if (threadIdx.x == 0) {
        __threadfence();
        unsigned e = g_epoch;
        if (atomicAdd(&g_barcnt, 1u) == NBLK - 1u) {
            g_barcnt = 0u;
            __threadfence();
            g_epoch = e + 1u;
        } else {
            while (g_epoch == e) { }
        }
        __threadfence();
    }
    __syncthreads();
}

// Bit-exact jax.random.bernoulli(jax.random.key(42), 0.5, (512,2,32,256)) * 2.0
// (jax_threefry_partitionable=True): per flat element i, threefry2x32 with key
// (0,42) on count pair (0, i); random word = out_x0 XOR out_x1; keep if top bit clear.
__device__ float drop_mask(unsigned idx) {
    unsigned x0 = 0u, x1 = idx;
    const unsigned ks0 = 0u, ks1 = 42u, ks2 = 0x1BD11BDAu ^ 42u;
    x0 += ks0; x1 += ks1;
#define RND(r) { x0 += x1; x1 = rotl(x1, r); x1 ^= x0; }
    RND(13) RND(15) RND(26) RND(6)  x0 += ks1; x1 += ks2 + 1u;
    RND(17) RND(29) RND(16) RND(24) x0 += ks2; x1 += ks0 + 2u;
    RND(13) RND(15) RND(26) RND(6)  x0 += ks0; x1 += ks1 + 3u;
    RND(17) RND(29) RND(16) RND(24) x0 += ks1; x1 += ks2 + 4u;
    RND(13) RND(15) RND(26) RND(6)  x0 += ks2; x1 += ks0 + 5u;
#undef RND
    unsigned bits = x0 ^ x1;
    return (bits & 0x80000000u) ? 0.0f : 2.0f;
}

// ---------------- setup kernels ----------------
__global__ void k_zero() {
    int i = blockIdx.x * blockDim.x + threadIdx.x;
    int n = blockDim.x * gridDim.x;
    for (int idx = i; idx < B32*KA;   idx += n) g_cat_a[idx] = 0.f;
    for (int idx = i; idx < B32*KD;   idx += n) g_cat_d[idx] = 0.f;
    for (int idx = i; idx < B32*HID;  idx += n) { g_ac[idx] = 0.f; g_dc[idx] = 0.f; }
    for (int idx = i; idx < B32*TENC; idx += n) { g_aw[idx] = 0.f; g_awc[idx] = 0.f; }
}

// out[k][r] = (k < K1 ? in1[r][k] : in2[r][k-K1]);  K = K1+K2 total cols, R rows.
__global__ void k_concatT(float* __restrict__ out, const float* __restrict__ in1,
                          const float* __restrict__ in2, int K1, int K2, int R) {
    __shared__ float tile[32][33];
    int K = K1 + K2;
    int k = blockIdx.x * 32 + threadIdx.x;
    int r = blockIdx.y * 32 + threadIdx.y;
    float v = 0.f;
    if (k < K && r < R) v = (k < K1) ? in1[(size_t)r * K1 + k] : in2[(size_t)r * K2 + (k - K1)];
    tile[threadIdx.y][threadIdx.x] = v;
    __syncthreads();
    int ko = blockIdx.x * 32 + threadIdx.y;
    int ro = blockIdx.y * 32 + threadIdx.x;
    if (ko < K && ro < R) out[(size_t)ko * R + ro] = tile[threadIdx.x][threadIdx.y];
}

__global__ void k_bias(const float* bih_a, const float* bhh_a,
                       const float* bih_d, const float* bhh_d) {
    int i = blockIdx.x * blockDim.x + threadIdx.x;
    if (i < R4) { g_ba[i] = bih_a[i] + bhh_a[i]; g_bd[i] = bih_d[i] + bhh_d[i]; }
}

// keys[b][t][a] = sum_d memory[b][t][d] * Wm[a][d]
__global__ void __launch_bounds__(128) k_keys(const float* __restrict__ memory) {
    int b = blockIdx.x, tc = blockIdx.y;
    __shared__ __align__(16) float sM[16 * EDIM];
    int t = threadIdx.x;
    for (int i = t; i < 16 * EDIM; i += 128) {
        int tt = i >> 9, d = i & 511;
        sM[i] = memory[((size_t)(b * TENC + tc * 16 + tt)) * EDIM + d];
    }
    __syncthreads();
    float acc[16];
#pragma unroll
    for (int j = 0; j < 16; j++) acc[j] = 0.f;
    int a = t;
    for (int d4 = 0; d4 < EDIM / 4; d4++) {
        float w0 = g_Wmt[(d4 * 4 + 0) * ATT + a];
        float w1 = g_Wmt[(d4 * 4 + 1) * ATT + a];
        float w2 = g_Wmt[(d4 * 4 + 2) * ATT + a];
        float w3 = g_Wmt[(d4 * 4 + 3) * ATT + a];
#pragma unroll
        for (int tt = 0; tt < 16; tt++) {
            float4 m = *(const float4*)&sM[tt * EDIM + d4 * 4];
            acc[tt] += m.x * w0 + m.y * w1 + m.z * w2 + m.w * w3;
        }
    }
    for (int tt = 0; tt < 16; tt++)
        g_keys[((size_t)(b * TENC + tc * 16 + tt)) * ATT + a] = acc[tt];
}

// Precompute prenet outputs for all 512 steps (teacher forcing + exact dropout).
__global__ void __launch_bounds__(256) k_prenet(const float* __restrict__ mel_target,
                                                const float* __restrict__ b_p1,
                                                const float* __restrict__ b_p2) {
    int t = blockIdx.x;
    int j = threadIdx.x;
    __shared__ __align__(16) float sDec[B32 * NMELS];
    __shared__ __align__(16) float sX1[B32 * PRE];
    for (int i = j; i < B32 * NMELS; i += 256) {
        int b = i / NMELS, m = i % NMELS;
        sDec[i] = (t == 0) ? 0.f : mel_target[((size_t)(b * NMELS + m)) * TDEC + (t - 1)];
    }
    __syncthreads();
    float acc[B32];
#pragma unroll
    for (int b = 0; b < B32; b++) acc[b] = 0.f;
    for (int m4 = 0; m4 < NMELS / 4; m4++) {
        float w0 = g_Wp1t[(4 * m4 + 0) * PRE + j];
        float w1 = g_Wp1t[(4 * m4 + 1) * PRE + j];
        float w2 = g_Wp1t[(4 * m4 + 2) * PRE + j];
        float w3 = g_Wp1t[(4 * m4 + 3) * PRE + j];
#pragma unroll
        for (int b = 0; b < B32; b++) {
            float4 d = *(const float4*)&sDec[b * NMELS + 4 * m4];
            acc[b] += d.x * w0 + d.y * w1 + d.z * w2 + d.w * w3;
        }
    }
    float bb = b_p1[j];
#pragma unroll
    for (int b = 0; b < B32; b++) {
        float v = acc[b] + bb; v = v > 0.f ? v : 0.f;
        v *= drop_mask(((unsigned)(t * 2 + 0) * B32 + b) * PRE + j);
        sX1[b * PRE + j] = v;
    }
    __syncthreads();
#pragma unroll
    for (int b = 0; b < B32; b++) acc[b] = 0.f;
    for (int k4 = 0; k4 < PRE / 4; k4++) {
        float w0 = g_Wp2t[(4 * k4 + 0) * PRE + j];
        float w1 = g_Wp2t[(4 * k4 + 1) * PRE + j];
        float w2 = g_Wp2t[(4 * k4 + 2) * PRE + j];
        float w3 = g_Wp2t[(4 * k4 + 3) * PRE + j];
#pragma unroll
        for (int b = 0; b < B32; b++) {
            float4 x = *(const float4*)&sX1[b * PRE + 4 * k4];
            acc[b] += x.x * w0 + x.y * w1 + x.z * w2 + x.w * w3;
        }
    }
    bb = b_p2[j];
#pragma unroll
    for (int b = 0; b < B32; b++) {
        float v = acc[b] + bb; v = v > 0.f ? v : 0.f;
        v *= drop_mask(((unsigned)(t * 2 + 1) * B32 + b) * PRE + j);
        g_X[((size_t)(t * B32 + b)) * PRE + j] = v;
    }
}

// ---------------- persistent-kernel phase bodies ----------------

// Double-buffered split-K GEMM: block (ntile, s) = (bx&31, bx>>5).
// smem layout: As[2][512] at sh[0..1023], Ws[2][2048] at sh[1024..5119].
template <int K>
__device__ __forceinline__ void gemm_phase(const float* __restrict__ A,
                                           const float* __restrict__ W,
                                           float* __restrict__ zp,
                                           float* __restrict__ sh) {
    const int KC = K / SPLT;
    const int NIT = KC / 16;
    int bx = blockIdx.x;
    int ntile = bx & 31, s = bx >> 5;
    int n0 = ntile * 128;
    int k0 = s * KC;
    int t = threadIdx.x;
    int bq = (t & 7) * 4;
    int nq = (t >> 3) * 4;
    int lb = t >> 3;
    int lk2 = (t & 7) * 2;
    int lkk = t >> 4;
    int ln8 = (t & 15) * 8;

    float acc[4][4];
#pragma unroll
    for (int i = 0; i < 4; i++)
#pragma unroll
        for (int j = 0; j < 4; j++) acc[i][j] = 0.f;

    float2 ra;
    float4 rw0, rw1;
    {   // preload iteration 0
        const float* asrc = A + (size_t)lb * K + k0 + lk2;
        ra = *(const float2*)asrc;
        const float* wsrc = W + (size_t)(k0 + lkk) * R4 + n0 + ln8;
        rw0 = *(const float4*)wsrc;
        rw1 = *(const float4*)(wsrc + 4);
        sh[lk2 * 32 + lb] = ra.x; sh[(lk2 + 1) * 32 + lb] = ra.y;
        *(float4*)&sh[1024 + lkk * 128 + ln8] = rw0;
        *(float4*)&sh[1024 + lkk * 128 + ln8 + 4] = rw1;
    }
    __syncthreads();

    for (int it = 0; it < NIT; it++) {
        if (it + 1 < NIT) {   // issue next tile's loads (latency hidden by compute)
            int kb = k0 + (it + 1) * 16;
            const float* asrc = A + (size_t)lb * K + kb + lk2;
            ra = *(const float2*)asrc;
            const float* wsrc = W + (size_t)(kb + lkk) * R4 + n0 + ln8;
            rw0 = *(const float4*)wsrc;
            rw1 = *(const float4*)(wsrc + 4);
        }
        const float* As = sh + (it & 1) * 512;
        const float* Ws = sh + 1024 + (it & 1) * 2048;
#pragma unroll
        for (int kk = 0; kk < 16; kk++) {
            float4 av = *(const float4*)&As[kk * 32 + bq];
            float4 wv = *(const float4*)&Ws[kk * 128 + nq];
            acc[0][0] += av.x * wv.x; acc[0][1] += av.x * wv.y; acc[0][2] += av.x * wv.z; acc[0][3] += av.x * wv.w;
            acc[1][0] += av.y * wv.x; acc[1][1] += av.y * wv.y; acc[1][2] += av.y * wv.z; acc[1][3] += av.y * wv.w;
            acc[2][0] += av.z * wv.x; acc[2][1] += av.z * wv.y; acc[2][2] += av.z * wv.z; acc[2][3] += av.z * wv.w;
            acc[3][0] += av.w * wv.x; acc[3][1] += av.w * wv.y; acc[3][2] += av.w * wv.z; acc[3][3] += av.w * wv.w;
        }
        if (it + 1 < NIT) {
            float* Asn = sh + ((it + 1) & 1) * 512;
            float* Wsn = sh + 1024 + ((it + 1) & 1) * 2048;
            Asn[lk2 * 32 + lb] = ra.x; Asn[(lk2 + 1) * 32 + lb] = ra.y;
            *(float4*)&Wsn[lkk * 128 + ln8] = rw0;
            *(float4*)&Wsn[lkk * 128 + ln8 + 4] = rw1;
            __syncthreads();
        }
    }
#pragma unroll
    for (int i = 0; i < 4; i++) {
        float4 v = make_float4(acc[i][0], acc[i][1], acc[i][2], acc[i][3]);
        *(float4*)&zp[((size_t)(s * B32 + bq + i)) * R4 + n0 + nq] = v;
    }
}

// combine attention-LSTM gates -> ah, ac; then q = ah @ Wq.T   (b = block index)
__device__ __forceinline__ void combineA_phase(int b, float* __restrict__ sh) {
    int t = threadIdx.x;
    float* sAh = sh;          // [1024]
    float* sQ = sh + 1024;    // [2][128]
#pragma unroll
    for (int u = 0; u < 4; u++) {
        int h = u * 256 + t;
        float zi = g_ba[h], zf = g_ba[HID + h], zg = g_ba[2 * HID + h], zo = g_ba[3 * HID + h];
#pragma unroll
        for (int s = 0; s < SPLT; s++) {
            const float* zp = &g_zpA[((size_t)(s * B32 + b)) * R4];
            zi += zp[h]; zf += zp[HID + h]; zg += zp[2 * HID + h]; zo += zp[3 * HID + h];
        }
        float c = sigm(zf) * g_ac[b * HID + h] + sigm(zi) * tanhf(zg);
        float hn = sigm(zo) * tanhf(c);
        g_ac[b * HID + h] = c;
        sAh[h] = hn;
        g_cat_a[b * KA + 768 + h] = hn;
        g_cat_d[b * KD + h] = hn;
    }
    __syncthreads();
    int a = t & 127, half = t >> 7;
    float acc = 0.f;
    int j0 = half * 512;
    for (int j = 0; j < 512; j++)
        acc += sAh[j0 + j] * g_Wqt[(j0 + j) * ATT + a];
    sQ[half * ATT + a] = acc;
    __syncthreads();
    if (t < ATT) g_q[b * ATT + t] = sQ[t] + sQ[ATT + t];
}

// location conv + loc projection + tanh energies (masked) for a 64-t chunk (all 128 blocks)
__device__ __forceinline__ void att1_phase(const float* __restrict__ W_loc,
                                           const float* __restrict__ b_loc,
                                           const float* __restrict__ Wv,
                                           const int* __restrict__ mem_len,
                                           float* __restrict__ sh) {
    int bx = blockIdx.x;
    int b = bx & 31, tc = bx >> 5;
    int t = threadIdx.x;
    int tbase = tc * 64;
    float* sAw0 = sh;            // 96
    float* sAw1 = sh + 96;       // 96
    float* sQ   = sh + 192;      // 128
    float* sWl  = sh + 320;      // 1984
    float* sLoc = sh + 2304;     // 64*32
    float* sEp  = sh + 4352;     // 8*32
    if (t < ATT) sQ[t] = g_q[b * ATT + t];
    for (int i = t; i < 94; i += 256) {
        int tt = tbase - 15 + i;
        bool ok = (tt >= 0) && (tt < TENC);
        sAw0[i] = ok ? g_aw[b * TENC + tt] : 0.f;
        sAw1[i] = ok ? g_awc[b * TENC + tt] : 0.f;
    }
    for (int i = t; i < LOCF * 2 * LOCK; i += 256) sWl[i] = W_loc[i];
    __syncthreads();
    for (int i = t; i < 64 * LOCF; i += 256) {
        int f = i & 31, tt = i >> 5;
        float acc = b_loc[f];
        const float* w0 = &sWl[f * 62];
        const float* w1 = &sWl[f * 62 + 31];
#pragma unroll
        for (int k = 0; k < 31; k++)
            acc += sAw0[tt + k] * w0[k] + sAw1[tt + k] * w1[k];
        sLoc[tt * 32 + f] = acc;
    }
    __syncthreads();
    int a = t & 127;
    int half = t >> 7;
    float wld[32];
#pragma unroll
    for (int f = 0; f < 32; f++) wld[f] = g_Wldt[f * ATT + a];
    float wv = Wv[a];
    float qa = sQ[a];
    int lane = t & 31, w = t >> 5;
    for (int tl = 0; tl < 32; tl++) {
        int tt = half * 32 + tl;
        float lA = 0.f;
#pragma unroll
        for (int f = 0; f < 32; f++) lA += sLoc[tt * 32 + f] * wld[f];
        float v = tanhf(qa + g_keys[((size_t)(b * TENC + tbase + tt)) * ATT + a] + lA) * wv;
        for (int off = 16; off; off >>= 1) v += __shfl_down_sync(0xffffffffu, v, off);
        if (lane == 0) sEp[w * 32 + tl] = v;
    }
    __syncthreads();
    int L = mem_len[b];
    for (int tt = t; tt < 64; tt += 256) {
        float e;
        if (tt < 32) e = sEp[tt] + sEp[32 + tt] + sEp[64 + tt] + sEp[96 + tt];
        else { int tl = tt - 32; e = sEp[128 + tl] + sEp[160 + tl] + sEp[192 + tl] + sEp[224 + tl]; }
        int tg = tbase + tt;
        g_e[b * TENC + tg] = (tg >= L) ? -1e30f : e;
    }
}

// softmax -> aw, awc, alignments, ctx   (blocks 0..31)
__device__ __forceinline__ void att2_phase(const float* __restrict__ memory,
                                           float* __restrict__ dout, int tstep,
                                           float* __restrict__ sh) {
    int b = blockIdx.x, t = threadIdx.x;
    float* sE = sh;
    float* sR1 = sh + 256;
    float* sR2 = sh + 264;
    sE[t] = g_e[b * TENC + t];
    __syncthreads();
    float v = sE[t];
    for (int off = 16; off; off >>= 1) v = fmaxf(v, __shfl_down_sync(0xffffffffu, v, off));
    if ((t & 31) == 0) sR1[t >> 5] = v;
    __syncthreads();
    if (t < 8) {
        float m = sR1[t];
        for (int off = 4; off; off >>= 1) m = fmaxf(m, __shfl_down_sync(0xffu, m, off));
        if (t == 0) sR1[0] = m;
    }
    __syncthreads();
    float mx = sR1[0];
    float p = expf(sE[t] - mx);
    float sv = p;
    for (int off = 16; off; off >>= 1) sv += __shfl_down_sync(0xffffffffu, sv, off);
    if ((t & 31) == 0) sR2[t >> 5] = sv;
    __syncthreads();
    if (t < 8) {
        float m = sR2[t];
        for (int off = 4; off; off >>= 1) m += __shfl_down_sync(0xffu, m, off);
        if (t == 0) sR2[0] = m;
    }
    __syncthreads();
    float aw = p / sR2[0];
    __syncthreads();
    sE[t] = aw;
    g_aw[b * TENC + t] = aw;
    g_awc[b * TENC + t] += aw;
    dout[ALIGN_OFF + ((size_t)(b * TDEC + tstep)) * TENC + t] = aw;
    __syncthreads();
    int d = t;
    float acc0 = 0.f, acc1 = 0.f;
    for (int tt = 0; tt < TENC; tt++) {
        float a = sE[tt];
        const float* mrow = &memory[((size_t)(b * TENC + tt)) * EDIM];
        acc0 += a * mrow[d];
        acc1 += a * mrow[d + 256];
    }
    g_cat_a[b * KA + 256 + d] = acc0;
    g_cat_a[b * KA + 256 + d + 256] = acc1;
    g_cat_d[b * KD + HID + d] = acc0;
    g_cat_d[b * KD + HID + d + 256] = acc1;
}

// combine decoder-LSTM gates -> dh, dc; then mel/gate projections  (b = block - 32)
__device__ __forceinline__ void combineD_phase(int b,
                                               const float* __restrict__ W_lin,
                                               const float* __restrict__ b_lin,
                                               const float* __restrict__ W_gate,
                                               const float* __restrict__ b_gate,
                                               float* __restrict__ dout, int tstep,
                                               float* __restrict__ sh) {
    int t = threadIdx.x;
    float* sOut = sh;        // [1536]
#pragma unroll
    for (int u = 0; u < 4; u++) {
        int h = u * 256 + t;
        float zi = g_bd[h], zf = g_bd[HID + h], zg = g_bd[2 * HID + h], zo = g_bd[3 * HID + h];
#pragma unroll
        for (int s = 0; s < SPLT; s++) {
            const float* zp = &g_zpD[((size_t)(s * B32 + b)) * R4];
            zi += zp[h]; zf += zp[HID + h]; zg += zp[2 * HID + h]; zo += zp[3 * HID + h];
        }
        float c = sigm(zf) * g_dc[b * HID + h] + sigm(zi) * tanhf(zg);
        float hn = sigm(zo) * tanhf(c);
        g_dc[b * HID + h] = c;
        g_cat_d[b * KD + 1536 + h] = hn;
        sOut[h] = hn;
    }
    for (int i = t; i < EDIM; i += 256) sOut[HID + i] = g_cat_d[b * KD + HID + i];
    __syncthreads();
    int lane = t & 31, w = t >> 5;
    for (int m = w; m < 81; m += 8) {
        const float* row; float bias;
        if (m < 80) { row = W_lin + (size_t)m * 1536; bias = b_lin[m]; }
        else        { row = W_gate; bias = b_gate[0]; }
        float acc = 0.f;
        for (int k = lane; k < 1536; k += 32) acc += sOut[k] * row[k];
        for (int off = 16; off; off >>= 1) acc += __shfl_down_sync(0xffffffffu, acc, off);
        if (lane == 0) {
            float r = acc + bias;
            if (m < 80) dout[((size_t)(b * NMELS + m)) * TDEC + tstep] = r;
            else        dout[GATE_OFF + b * TDEC + tstep] = r;
        }
    }
}

// copy x(t) into cat_a's x slot (blocks basebx..basebx+31)
__device__ __forceinline__ void xcopy_phase(int b, int tstep) {
    int t = threadIdx.x;
    g_cat_a[b * KA + t] = g_X[((size_t)(tstep * B32 + b)) * PRE + t];
}

// ---------------- the persistent 512-step kernel ----------------
// Schedule (5 grid barriers per step):
//   P1: GEMM-A(t)                              [all 128 blocks]
//   P2: combineA(t)   [blk 0-31]
//       combineD(t-1) [blk 32-63, t>0]
//       x-copy(t+1)   [blk 64-95, t<511]
//   P3: att1(t)                                [all 128 blocks]
//   P4: att2(t)       [blk 0-31]
//   P5: GEMM-D(t)                              [all 128 blocks]
// post-loop: combineD(511) [blk 32-63]
__global__ void __launch_bounds__(NTHR) k_steps(const float* __restrict__ memory,
                                                const float* __restrict__ W_loc,
                                                const float* __restrict__ b_loc,
                                                const float* __restrict__ Wv,
                                                const int* __restrict__ mem_len,
                                                const float* __restrict__ W_lin,
                                                const float* __restrict__ b_lin,
                                                const float* __restrict__ W_gate,
                                                const float* __restrict__ b_gate,
                                                float* __restrict__ dout) {
    __shared__ __align__(16) float sh[5120];
    int bx = blockIdx.x;

    // pre-loop: x(0) into cat_a
    if (bx < 32) xcopy_phase(bx, 0);
    gsync();

    for (int t = 0; t < TDEC; t++) {
        gemm_phase<KA>(g_cat_a, g_WaT, g_zpA, sh);
        gsync();
        if (bx < 32)                combineA_phase(bx, sh);
        else if (bx < 64 && t > 0)  combineD_phase(bx - 32, W_lin, b_lin, W_gate, b_gate, dout, t - 1, sh);
        else if (bx >= 64 && bx < 96 && t + 1 < TDEC) xcopy_phase(bx - 64, t + 1);
        gsync();
        att1_phase(W_loc, b_loc, Wv, mem_len, sh);
        gsync();
        if (bx < 32) att2_phase(memory, dout, t, sh);
        gsync();
        gemm_phase<KD>(g_cat_d, g_WdT, g_zpD, sh);
        gsync();
    }
    if (bx >= 32 && bx < 64)
        combineD_phase(bx - 32, W_lin, b_lin, W_gate, b_gate, dout, TDEC - 1, sh);
}

// ---------------- host ----------------
extern "C" void kernel_launch(void* const* d_in, const int* in_sizes, int n_in,
                              void* d_out, int out_size) {
    const float* memory   = (const float*)d_in[0];
    const float* mel_tgt  = (const float*)d_in[1];
    const int*   mem_len  = (const int*)  d_in[2];
    const float* W_p1     = (const float*)d_in[3];
    const float* b_p1     = (const float*)d_in[4];
    const float* W_p2     = (const float*)d_in[5];
    const float* b_p2     = (const float*)d_in[6];
    const float* Wih_a    = (const float*)d_in[7];
    const float* Whh_a    = (const float*)d_in[8];
    const float* bih_a    = (const float*)d_in[9];
    const float* bhh_a    = (const float*)d_in[10];
    const float* Wq       = (const float*)d_in[11];
    const float* Wm       = (const float*)d_in[12];
    const float* Wv       = (const float*)d_in[13];
    const float* W_loc    = (const float*)d_in[14];
    const float* b_loc    = (const float*)d_in[15];
    const float* W_locd   = (const float*)d_in[16];
    const float* Wih_d    = (const float*)d_in[17];
    const float* Whh_d    = (const float*)d_in[18];
    const float* bih_d    = (const float*)d_in[19];
    const float* bhh_d    = (const float*)d_in[20];
    const float* W_lin    = (const float*)d_in[21];
    const float* b_lin    = (const float*)d_in[22];
    const float* W_gate   = (const float*)d_in[23];
    const float* b_gate   = (const float*)d_in[24];
    float* out = (float*)d_out;

    float *WaT, *WdT, *Wqt, *Wmt, *Wp1t, *Wp2t, *Wldt;
    cudaGetSymbolAddress((void**)&WaT,  g_WaT);
    cudaGetSymbolAddress((void**)&WdT,  g_WdT);
    cudaGetSymbolAddress((void**)&Wqt,  g_Wqt);
    cudaGetSymbolAddress((void**)&Wmt,  g_Wmt);
    cudaGetSymbolAddress((void**)&Wp1t, g_Wp1t);
    cudaGetSymbolAddress((void**)&Wp2t, g_Wp2t);
    cudaGetSymbolAddress((void**)&Wldt, g_Wldt);

    dim3 tb(32, 32);
    k_zero<<<256, 256>>>();
    k_concatT<<<dim3(KA / 32, R4 / 32), tb>>>(WaT, Wih_a, Whh_a, 768, 1024, R4);
    k_concatT<<<dim3(KD / 32, R4 / 32), tb>>>(WdT, Wih_d, Whh_d, 1536, 1024, R4);
    k_concatT<<<dim3(32, 4),  tb>>>(Wqt,  Wq,     Wq,     1024, 0, 128);
    k_concatT<<<dim3(16, 4),  tb>>>(Wmt,  Wm,     Wm,     512,  0, 128);
    k_concatT<<<dim3(3, 8),   tb>>>(Wp1t, W_p1,   W_p1,   80,   0, 256);
    k_concatT<<<dim3(8, 8),   tb>>>(Wp2t, W_p2,   W_p2,   256,  0, 256);
    k_concatT<<<dim3(1, 4),   tb>>>(Wldt, W_locd, W_locd, 32,   0, 128);
    k_bias<<<16, 256>>>(bih_a, bhh_a, bih_d, bhh_d);
    k_keys<<<dim3(32, 16), 128>>>(memory);
    k_prenet<<<512, 256>>>(mel_tgt, b_p1, b_p2);

    k_steps<<<NBLK, NTHR>>>(memory, W_loc, b_loc, Wv, mem_len,
                            W_lin, b_lin, W_gate, b_gate, out);
}

// round 13
// speedup vs baseline: 1.5294x; 1.5294x over previous
#include <cuda_runtime.h>
#include <math.h>

// ---------------- problem constants ----------------
#define B32    32
#define TENC   256
#define TDEC   512
#define NMELS  80
#define EDIM   512
#define PRE    256
#define HID    1024
#define ATT    128
#define LOCF   32
#define LOCK   31
#define KA     1792           // PRE + EDIM + HID  (x | ctx | ah)
#define KD     2560           // HID + EDIM + HID  (ah | ctx | dh)
#define R4     4096
#define NBLK   128
#define NTHR   256

#define MEL_SZ    (B32*NMELS*TDEC)
#define GATE_OFF  MEL_SZ
#define ALIGN_OFF (MEL_SZ + B32*TDEC)

// ---------------- static device buffers ----------------
__device__ float g_WaT[KA*R4];       // [k][r]
__device__ float g_WdT[KD*R4];       // [k][r]
__device__ float g_keys[B32*TENC*ATT];
__device__ float g_X[TDEC*B32*PRE];  // precomputed prenet outputs
__device__ float g_zpA[4*B32*R4];    // split-K partials (attention LSTM)
__device__ float g_zpD[4*B32*R4];    // split-K partials (decoder LSTM)
__device__ float g_Wqt[HID*ATT];
__device__ float g_Wmt[EDIM*ATT];
__device__ float g_Wp1t[NMELS*PRE];
__device__ float g_Wp2t[PRE*PRE];
__device__ float g_Wldt[LOCF*ATT];
__device__ float g_ba[R4];
__device__ float g_bd[R4];
__device__ float g_cat_a[B32*KA];    // [x | ctx | ah]
__device__ float g_cat_d[B32*KD];    // [ah | ctx | dh]
__device__ float g_ac[B32*HID];
__device__ float g_dc[B32*HID];
__device__ float g_aw[B32*TENC];
__device__ float g_awc[B32*TENC];
__device__ float g_q[B32*ATT];
__device__ float g_e[B32*TENC];

// sync state
__device__ unsigned g_barcnt = 0;
__device__ volatile unsigned g_epoch = 0;
__device__ unsigned g_fq = 0;        // combineA -> att1-energy flag (reset each replay)
__device__ unsigned g_fctx = 0;      // att2 -> GEMM-D ctx flag     (reset each replay)

__device__ __forceinline__ float sigm(float x) { return 1.0f / (1.0f + expf(-x)); }
__device__ __forceinline__ unsigned rotl(unsigned x, int d) { return (x << d) | (x >> (32 - d)); }

__device__ __forceinline__ void gsync() {
    __syncthreads();
    if (threadIdx.x == 0) {
        __threadfence();
        unsigned e = g_epoch;
        if (atomicAdd(&g_barcnt, 1u) == NBLK - 1u) {
            g_barcnt = 0u;
            __threadfence();
            g_epoch = e + 1u;
        } else {
            while (g_epoch == e) { }
        }
        __threadfence();
    }
    __syncthreads();
}

// acquire-wait on a monotone flag counter
__device__ __forceinline__ void flag_wait(unsigned* flag, unsigned target) {
    if (threadIdx.x == 0) {
        while (*(volatile unsigned*)flag < target) { }
        __threadfence();
    }
    __syncthreads();
}

// Bit-exact jax.random.bernoulli(jax.random.key(42), 0.5, (512,2,32,256)) * 2.0
// (jax_threefry_partitionable=True): per flat element i, threefry2x32 with key
// (0,42) on count pair (0, i); random word = out_x0 XOR out_x1; keep if top bit clear.
__device__ float drop_mask(unsigned idx) {
    unsigned x0 = 0u, x1 = idx;
    const unsigned ks0 = 0u, ks1 = 42u, ks2 = 0x1BD11BDAu ^ 42u;
    x0 += ks0; x1 += ks1;
#define RND(r) { x0 += x1; x1 = rotl(x1, r); x1 ^= x0; }
    RND(13) RND(15) RND(26) RND(6)  x0 += ks1; x1 += ks2 + 1u;
    RND(17) RND(29) RND(16) RND(24) x0 += ks2; x1 += ks0 + 2u;
    RND(13) RND(15) RND(26) RND(6)  x0 += ks0; x1 += ks1 + 3u;
    RND(17) RND(29) RND(16) RND(24) x0 += ks1; x1 += ks2 + 4u;
    RND(13) RND(15) RND(26) RND(6)  x0 += ks2; x1 += ks0 + 5u;
#undef RND
    unsigned bits = x0 ^ x1;
    return (bits & 0x80000000u) ? 0.0f : 2.0f;
}

// ---------------- setup kernels (exactly 5 launches before k_steps) ----------------
// launch 0: zero state + flags, fused biases, all small transposes
__global__ void k_setup(const float* bih_a, const float* bhh_a,
                        const float* bih_d, const float* bhh_d,
                        const float* Wq, const float* Wm, const float* Wp1,
                        const float* Wp2, const float* Wld) {
    int i0 = blockIdx.x * blockDim.x + threadIdx.x;
    int n = blockDim.x * gridDim.x;
    for (int i = i0; i < B32*KA;   i += n) g_cat_a[i] = 0.f;
    for (int i = i0; i < B32*KD;   i += n) g_cat_d[i] = 0.f;
    for (int i = i0; i < B32*HID;  i += n) { g_ac[i] = 0.f; g_dc[i] = 0.f; }
    for (int i = i0; i < B32*TENC; i += n) { g_aw[i] = 0.f; g_awc[i] = 0.f; }
    for (int i = i0; i < R4;       i += n) { g_ba[i] = bih_a[i] + bhh_a[i]; g_bd[i] = bih_d[i] + bhh_d[i]; }
    for (int i = i0; i < HID*ATT;  i += n) { int k = i >> 7, a = i & 127; g_Wqt[i]  = Wq[a*HID + k]; }
    for (int i = i0; i < EDIM*ATT; i += n) { int k = i >> 7, a = i & 127; g_Wmt[i]  = Wm[a*EDIM + k]; }
    for (int i = i0; i < NMELS*PRE;i += n) { int m = i >> 8, j = i & 255; g_Wp1t[i] = Wp1[j*NMELS + m]; }
    for (int i = i0; i < PRE*PRE;  i += n) { int k = i >> 8, j = i & 255; g_Wp2t[i] = Wp2[j*PRE + k]; }
    for (int i = i0; i < LOCF*ATT; i += n) { int f = i >> 7, a = i & 127; g_Wldt[i] = Wld[a*LOCF + f]; }
    if (i0 == 0) { g_fq = 0u; g_fctx = 0u; }
}

// out[k][r] = (k < K1 ? in1[r][k] : in2[r][k-K1]);  K = K1+K2 total cols, R rows.
__global__ void k_concatT(float* __restrict__ out, const float* __restrict__ in1,
                          const float* __restrict__ in2, int K1, int K2, int R) {
    __shared__ float tile[32][33];
    int K = K1 + K2;
    int k = blockIdx.x * 32 + threadIdx.x;
    int r = blockIdx.y * 32 + threadIdx.y;
    float v = 0.f;
    if (k < K && r < R) v = (k < K1) ? in1[(size_t)r * K1 + k] : in2[(size_t)r * K2 + (k - K1)];
    tile[threadIdx.y][threadIdx.x] = v;
    __syncthreads();
    int ko = blockIdx.x * 32 + threadIdx.y;
    int ro = blockIdx.y * 32 + threadIdx.x;
    if (ko < K && ro < R) out[(size_t)ko * R + ro] = tile[threadIdx.x][threadIdx.y];
}

// keys[b][t][a] = sum_d memory[b][t][d] * Wm[a][d]
__global__ void __launch_bounds__(128) k_keys(const float* __restrict__ memory) {
    int b = blockIdx.x, tc = blockIdx.y;
    __shared__ __align__(16) float sM[16 * EDIM];
    int t = threadIdx.x;
    for (int i = t; i < 16 * EDIM; i += 128) {
        int tt = i >> 9, d = i & 511;
        sM[i] = memory[((size_t)(b * TENC + tc * 16 + tt)) * EDIM + d];
    }
    __syncthreads();
    float acc[16];
#pragma unroll
    for (int j = 0; j < 16; j++) acc[j] = 0.f;
    int a = t;
    for (int d4 = 0; d4 < EDIM / 4; d4++) {
        float w0 = g_Wmt[(d4 * 4 + 0) * ATT + a];
        float w1 = g_Wmt[(d4 * 4 + 1) * ATT + a];
        float w2 = g_Wmt[(d4 * 4 + 2) * ATT + a];
        float w3 = g_Wmt[(d4 * 4 + 3) * ATT + a];
#pragma unroll
        for (int tt = 0; tt < 16; tt++) {
            float4 m = *(const float4*)&sM[tt * EDIM + d4 * 4];
            acc[tt] += m.x * w0 + m.y * w1 + m.z * w2 + m.w * w3;
        }
    }
    for (int tt = 0; tt < 16; tt++)
        g_keys[((size_t)(b * TENC + tc * 16 + tt)) * ATT + a] = acc[tt];
}

// Precompute prenet outputs for all 512 steps (teacher forcing + exact dropout).
__global__ void __launch_bounds__(256) k_prenet(const float* __restrict__ mel_target,
                                                const float* __restrict__ b_p1,
                                                const float* __restrict__ b_p2) {
    int t = blockIdx.x;
    int j = threadIdx.x;
    __shared__ __align__(16) float sDec[B32 * NMELS];
    __shared__ __align__(16) float sX1[B32 * PRE];
    for (int i = j; i < B32 * NMELS; i += 256) {
        int b = i / NMELS, m = i % NMELS;
        sDec[i] = (t == 0) ? 0.f : mel_target[((size_t)(b * NMELS + m)) * TDEC + (t - 1)];
    }
    __syncthreads();
    float acc[B32];
#pragma unroll
    for (int b = 0; b < B32; b++) acc[b] = 0.f;
    for (int m4 = 0; m4 < NMELS / 4; m4++) {
        float w0 = g_Wp1t[(4 * m4 + 0) * PRE + j];
        float w1 = g_Wp1t[(4 * m4 + 1) * PRE + j];
        float w2 = g_Wp1t[(4 * m4 + 2) * PRE + j];
        float w3 = g_Wp1t[(4 * m4 + 3) * PRE + j];
#pragma unroll
        for (int b = 0; b < B32; b++) {
            float4 d = *(const float4*)&sDec[b * NMELS + 4 * m4];
            acc[b] += d.x * w0 + d.y * w1 + d.z * w2 + d.w * w3;
        }
    }
    float bb = b_p1[j];
#pragma unroll
    for (int b = 0; b < B32; b++) {
        float v = acc[b] + bb; v = v > 0.f ? v : 0.f;
        v *= drop_mask(((unsigned)(t * 2 + 0) * B32 + b) * PRE + j);
        sX1[b * PRE + j] = v;
    }
    __syncthreads();
#pragma unroll
    for (int b = 0; b < B32; b++) acc[b] = 0.f;
    for (int k4 = 0; k4 < PRE / 4; k4++) {
        float w0 = g_Wp2t[(4 * k4 + 0) * PRE + j];
        float w1 = g_Wp2t[(4 * k4 + 1) * PRE + j];
        float w2 = g_Wp2t[(4 * k4 + 2) * PRE + j];
        float w3 = g_Wp2t[(4 * k4 + 3) * PRE + j];
#pragma unroll
        for (int b = 0; b < B32; b++) {
            float4 x = *(const float4*)&sX1[b * PRE + 4 * k4];
            acc[b] += x.x * w0 + x.y * w1 + x.z * w2 + x.w * w3;
        }
    }
    bb = b_p2[j];
#pragma unroll
    for (int b = 0; b < B32; b++) {
        float v = acc[b] + bb; v = v > 0.f ? v : 0.f;
        v *= drop_mask(((unsigned)(t * 2 + 1) * B32 + b) * PRE + j);
        g_X[((size_t)(t * B32 + b)) * PRE + j] = v;
    }
}

// ---------------- persistent-kernel phase bodies ----------------

// Double-buffered GEMM over k-chunks [c0,c1) of 16; accumulates into acc.
// smem: As[2][512] at sh[0..1023], Ws[2][2048] at sh[1024..5119].
template <int K>
__device__ __forceinline__ void gemm_chunks(const float* __restrict__ A,
                                            const float* __restrict__ W,
                                            float* __restrict__ sh,
                                            int k0, int c0, int c1,
                                            float (&acc)[4][4], int n0) {
    int nc = c1 - c0;
    if (nc <= 0) return;
    int t = threadIdx.x;
    int lb = t >> 3;
    int lk2 = (t & 7) * 2;
    int lkk = t >> 4;
    int ln8 = (t & 15) * 8;
    int bq = (t & 7) * 4;
    int nq = (t >> 3) * 4;

    float2 ra;
    float4 rw0, rw1;
    {
        int kb = k0 + c0 * 16;
        ra = *(const float2*)(A + (size_t)lb * K + kb + lk2);
        const float* wsrc = W + (size_t)(kb + lkk) * R4 + n0 + ln8;
        rw0 = *(const float4*)wsrc; rw1 = *(const float4*)(wsrc + 4);
        sh[lk2 * 32 + lb] = ra.x; sh[(lk2 + 1) * 32 + lb] = ra.y;
        *(float4*)&sh[1024 + lkk * 128 + ln8] = rw0;
        *(float4*)&sh[1024 + lkk * 128 + ln8 + 4] = rw1;
    }
    __syncthreads();
    for (int it = 0; it < nc; it++) {
        if (it + 1 < nc) {
            int kb = k0 + (c0 + it + 1) * 16;
            ra = *(const float2*)(A + (size_t)lb * K + kb + lk2);
            const float* wsrc = W + (size_t)(kb + lkk) * R4 + n0 + ln8;
            rw0 = *(const float4*)wsrc; rw1 = *(const float4*)(wsrc + 4);
        }
        const float* As = sh + (it & 1) * 512;
        const float* Ws = sh + 1024 + (it & 1) * 2048;
#pragma unroll
        for (int kk = 0; kk < 16; kk++) {
            float4 av = *(const float4*)&As[kk * 32 + bq];
            float4 wv = *(const float4*)&Ws[kk * 128 + nq];
            acc[0][0] += av.x * wv.x; acc[0][1] += av.x * wv.y; acc[0][2] += av.x * wv.z; acc[0][3] += av.x * wv.w;
            acc[1][0] += av.y * wv.x; acc[1][1] += av.y * wv.y; acc[1][2] += av.y * wv.z; acc[1][3] += av.y * wv.w;
            acc[2][0] += av.z * wv.x; acc[2][1] += av.z * wv.y; acc[2][2] += av.z * wv.z; acc[2][3] += av.z * wv.w;
            acc[3][0] += av.w * wv.x; acc[3][1] += av.w * wv.y; acc[3][2] += av.w * wv.z; acc[3][3] += av.w * wv.w;
        }
        if (it + 1 < nc) {
            float* Asn = sh + ((it + 1) & 1) * 512;
            float* Wsn = sh + 1024 + ((it + 1) & 1) * 2048;
            Asn[lk2 * 32 + lb] = ra.x; Asn[(lk2 + 1) * 32 + lb] = ra.y;
            *(float4*)&Wsn[lkk * 128 + ln8] = rw0;
            *(float4*)&Wsn[lkk * 128 + ln8 + 4] = rw1;
            __syncthreads();
        }
    }
    __syncthreads();   // buffers free for caller's next segment
}

__device__ __forceinline__ void zp_store(float* __restrict__ zp, float (&acc)[4][4],
                                         int s, int n0) {
    int t = threadIdx.x;
    int bq = (t & 7) * 4;
    int nq = (t >> 3) * 4;
#pragma unroll
    for (int i = 0; i < 4; i++) {
        float4 v = make_float4(acc[i][0], acc[i][1], acc[i][2], acc[i][3]);
        *(float4*)&zp[((size_t)(s * B32 + bq + i)) * R4 + n0 + nq] = v;
    }
}

// combineA: gates -> ah, ac; q = ah @ Wq.T; release g_fq
__device__ __forceinline__ void combineA_phase(int b, float* __restrict__ sh) {
    int t = threadIdx.x;
    float* sAh = sh;          // [1024]
    float* sQ = sh + 1024;    // [2][128]
#pragma unroll
    for (int u = 0; u < 4; u++) {
        int h = u * 256 + t;
        float zi = g_ba[h], zf = g_ba[HID + h], zg = g_ba[2 * HID + h], zo = g_ba[3 * HID + h];
#pragma unroll
        for (int s = 0; s < 4; s++) {
            const float* zp = &g_zpA[((size_t)(s * B32 + b)) * R4];
            zi += zp[h]; zf += zp[HID + h]; zg += zp[2 * HID + h]; zo += zp[3 * HID + h];
        }
        float c = sigm(zf) * g_ac[b * HID + h] + sigm(zi) * tanhf(zg);
        float hn = sigm(zo) * tanhf(c);
        g_ac[b * HID + h] = c;
        sAh[h] = hn;
        g_cat_a[b * KA + 768 + h] = hn;
        g_cat_d[b * KD + h] = hn;
    }
    __syncthreads();
    int a = t & 127, half = t >> 7;
    int j0 = half * 512;
    float a0 = 0.f, a1 = 0.f, a2 = 0.f, a3 = 0.f;
    for (int j = 0; j < 512; j += 4) {
        a0 += sAh[j0 + j]     * g_Wqt[(j0 + j) * ATT + a];
        a1 += sAh[j0 + j + 1] * g_Wqt[(j0 + j + 1) * ATT + a];
        a2 += sAh[j0 + j + 2] * g_Wqt[(j0 + j + 2) * ATT + a];
        a3 += sAh[j0 + j + 3] * g_Wqt[(j0 + j + 3) * ATT + a];
    }
    sQ[half * ATT + a] = (a0 + a1) + (a2 + a3);
    __syncthreads();
    if (t < ATT) g_q[b * ATT + t] = sQ[t] + sQ[ATT + t];
    __syncthreads();
    if (t == 0) { __threadfence(); atomicAdd(&g_fq, 1u); }
}

// att1: conv (t-1 state) -> wait q flag -> energies for a 64-t chunk
__device__ __forceinline__ void att1_phase(const float* __restrict__ W_loc,
                                           const float* __restrict__ b_loc,
                                           const float* __restrict__ Wv,
                                           const int* __restrict__ mem_len,
                                           unsigned fq_target,
                                           float* __restrict__ sh) {
    int bx = blockIdx.x;
    int b = bx & 31, tc = bx >> 5;
    int t = threadIdx.x;
    int tbase = tc * 64;
    float* sAw0 = sh;            // 96
    float* sAw1 = sh + 96;       // 96
    float* sQ   = sh + 192;      // 128
    float* sWl  = sh + 320;      // 1984
    float* sLoc = sh + 2304;     // 64*32
    float* sEp  = sh + 4352;     // 8*32
    for (int i = t; i < 94; i += 256) {
        int tt = tbase - 15 + i;
        bool ok = (tt >= 0) && (tt < TENC);
        sAw0[i] = ok ? g_aw[b * TENC + tt] : 0.f;
        sAw1[i] = ok ? g_awc[b * TENC + tt] : 0.f;
    }
    for (int i = t; i < LOCF * 2 * LOCK; i += 256) sWl[i] = W_loc[i];
    __syncthreads();
    for (int i = t; i < 64 * LOCF; i += 256) {
        int f = i & 31, tt = i >> 5;
        const float* w0 = &sWl[f * 62];
        const float* w1 = &sWl[f * 62 + 31];
        float c0 = b_loc[f], c1 = 0.f, c2 = 0.f, c3 = 0.f;
#pragma unroll
        for (int k = 0; k < 30; k += 2) {
            c0 += sAw0[tt + k] * w0[k];
            c1 += sAw0[tt + k + 1] * w0[k + 1];
            c2 += sAw1[tt + k] * w1[k];
            c3 += sAw1[tt + k + 1] * w1[k + 1];
        }
        c0 += sAw0[tt + 30] * w0[30];
        c2 += sAw1[tt + 30] * w1[30];
        sLoc[tt * 32 + f] = (c0 + c1) + (c2 + c3);
    }
    // wait for q(t), then load it
    flag_wait(&g_fq, fq_target);
    if (t < ATT) sQ[t] = g_q[b * ATT + t];
    __syncthreads();
    int a = t & 127;
    int half = t >> 7;
    float wld[32];
#pragma unroll
    for (int f = 0; f < 32; f++) wld[f] = g_Wldt[f * ATT + a];
    float wv = Wv[a];
    float qa = sQ[a];
    int lane = t & 31, w = t >> 5;
#pragma unroll 2
    for (int tl = 0; tl < 32; tl++) {
        int tt = half * 32 + tl;
        float l0 = 0.f, l1 = 0.f, l2 = 0.f, l3 = 0.f;
#pragma unroll
        for (int f = 0; f < 8; f++) {
            l0 += sLoc[tt * 32 + f]      * wld[f];
            l1 += sLoc[tt * 32 + f + 8]  * wld[f + 8];
            l2 += sLoc[tt * 32 + f + 16] * wld[f + 16];
            l3 += sLoc[tt * 32 + f + 24] * wld[f + 24];
        }
        float lA = (l0 + l1) + (l2 + l3);
        float v = tanhf(qa + g_keys[((size_t)(b * TENC + tbase + tt)) * ATT + a] + lA) * wv;
        for (int off = 16; off; off >>= 1) v += __shfl_down_sync(0xffffffffu, v, off);
        if (lane == 0) sEp[w * 32 + tl] = v;
    }
    __syncthreads();
    int L = mem_len[b];
    for (int tt = t; tt < 64; tt += 256) {
        float e;
        if (tt < 32) e = sEp[tt] + sEp[32 + tt] + sEp[64 + tt] + sEp[96 + tt];
        else { int tl = tt - 32; e = sEp[128 + tl] + sEp[160 + tl] + sEp[192 + tl] + sEp[224 + tl]; }
        int tg = tbase + tt;
        g_e[b * TENC + tg] = (tg >= L) ? -1e30f : e;
    }
}

// att2: softmax -> aw, awc, alignments, ctx   (blocks 0..31)
__device__ __forceinline__ void att2_phase(const float* __restrict__ memory,
                                           float* __restrict__ dout, int tstep,
                                           float* __restrict__ sh) {
    int b = blockIdx.x, t = threadIdx.x;
    float* sE = sh;
    float* sR1 = sh + 256;
    float* sR2 = sh + 264;
    sE[t] = g_e[b * TENC + t];
    __syncthreads();
    float v = sE[t];
    for (int off = 16; off; off >>= 1) v = fmaxf(v, __shfl_down_sync(0xffffffffu, v, off));
    if ((t & 31) == 0) sR1[t >> 5] = v;
    __syncthreads();
    if (t < 8) {
        float m = sR1[t];
        for (int off = 4; off; off >>= 1) m = fmaxf(m, __shfl_down_sync(0xffu, m, off));
        if (t == 0) sR1[0] = m;
    }
    __syncthreads();
    float mx = sR1[0];
    float p = expf(sE[t] - mx);
    float sv = p;
    for (int off = 16; off; off >>= 1) sv += __shfl_down_sync(0xffffffffu, sv, off);
    if ((t & 31) == 0) sR2[t >> 5] = sv;
    __syncthreads();
    if (t < 8) {
        float m = sR2[t];
        for (int off = 4; off; off >>= 1) m += __shfl_down_sync(0xffu, m, off);
        if (t == 0) sR2[0] = m;
    }
    __syncthreads();
    float aw = p / sR2[0];
    __syncthreads();
    sE[t] = aw;
    g_aw[b * TENC + t] = aw;
    g_awc[b * TENC + t] += aw;
    dout[ALIGN_OFF + ((size_t)(b * TDEC + tstep)) * TENC + t] = aw;
    __syncthreads();
    int d = t;
    float p00 = 0.f, p01 = 0.f, p02 = 0.f, p03 = 0.f;
    float p10 = 0.f, p11 = 0.f, p12 = 0.f, p13 = 0.f;
    for (int tt = 0; tt < TENC; tt += 4) {
        const float* m0 = &memory[((size_t)(b * TENC + tt)) * EDIM];
        float a0 = sE[tt], a1 = sE[tt + 1], a2 = sE[tt + 2], a3 = sE[tt + 3];
        p00 += a0 * m0[d];               p10 += a0 * m0[d + 256];
        p01 += a1 * m0[EDIM + d];        p11 += a1 * m0[EDIM + d + 256];
        p02 += a2 * m0[2 * EDIM + d];    p12 += a2 * m0[2 * EDIM + d + 256];
        p03 += a3 * m0[3 * EDIM + d];    p13 += a3 * m0[3 * EDIM + d + 256];
    }
    float acc0 = (p00 + p01) + (p02 + p03);
    float acc1 = (p10 + p11) + (p12 + p13);
    g_cat_a[b * KA + 256 + d] = acc0;
    g_cat_a[b * KA + 256 + d + 256] = acc1;
    g_cat_d[b * KD + HID + d] = acc0;
    g_cat_d[b * KD + HID + d + 256] = acc1;
    __syncthreads();
    if (t == 0) { __threadfence(); atomicAdd(&g_fctx, 1u); }
    __syncthreads();
}

// combineD: gates -> dh, dc; mel/gate projections   (b = block - 32)
__device__ __forceinline__ void combineD_phase(int b,
                                               const float* __restrict__ W_lin,
                                               const float* __restrict__ b_lin,
                                               const float* __restrict__ W_gate,
                                               const float* __restrict__ b_gate,
                                               float* __restrict__ dout, int tstep,
                                               float* __restrict__ sh) {
    int t = threadIdx.x;
    float* sOut = sh;        // [1536]
#pragma unroll
    for (int u = 0; u < 4; u++) {
        int h = u * 256 + t;
        float zi = g_bd[h], zf = g_bd[HID + h], zg = g_bd[2 * HID + h], zo = g_bd[3 * HID + h];
#pragma unroll
        for (int s = 0; s < 4; s++) {
            const float* zp = &g_zpD[((size_t)(s * B32 + b)) * R4];
            zi += zp[h]; zf += zp[HID + h]; zg += zp[2 * HID + h]; zo += zp[3 * HID + h];
        }
        float c = sigm(zf) * g_dc[b * HID + h] + sigm(zi) * tanhf(zg);
        float hn = sigm(zo) * tanhf(c);
        g_dc[b * HID + h] = c;
        g_cat_d[b * KD + 1536 + h] = hn;
        sOut[h] = hn;
    }
    for (int i = t; i < EDIM; i += 256) sOut[HID + i] = g_cat_d[b * KD + HID + i];
    __syncthreads();
    int lane = t & 31, w = t >> 5;
    for (int m = w; m < 81; m += 8) {
        const float* row; float bias;
        if (m < 80) { row = W_lin + (size_t)m * 1536; bias = b_lin[m]; }
        else        { row = W_gate; bias = b_gate[0]; }
        float a0 = 0.f, a1 = 0.f, a2 = 0.f, a3 = 0.f;
        for (int k = lane; k < 1536; k += 128) {
            a0 += sOut[k] * row[k];
            a1 += sOut[k + 32] * row[k + 32];
            a2 += sOut[k + 64] * row[k + 64];
            a3 += sOut[k + 96] * row[k + 96];
        }
        float acc = (a0 + a1) + (a2 + a3);
        for (int off = 16; off; off >>= 1) acc += __shfl_down_sync(0xffffffffu, acc, off);
        if (lane == 0) {
            float r = acc + bias;
            if (m < 80) dout[((size_t)(b * NMELS + m)) * TDEC + tstep] = r;
            else        dout[GATE_OFF + b * TDEC + tstep] = r;
        }
    }
}

__device__ __forceinline__ void xcopy_phase(int b, int tstep) {
    int t = threadIdx.x;
    g_cat_a[b * KA + t] = g_X[((size_t)(tstep * B32 + b)) * PRE + t];
}

// ---------------- the persistent 512-step kernel ----------------
// 3 grid barriers per step:
//  P_G1: GEMM-A(t)                                  [128 blocks] -- gsync
//  P_MID: [0-31 combineA(t)->fq | 32-63 combineD(t-1) | 64-95 xcopy(t+1)]
//         then all: att1 conv -> wait fq -> energies            -- gsync
//  P_G2:  blk 0-31: att2(t)->fctx then GEMM-D split0 (no ctx)
//         blk 32-127: GEMM-D with ctx chunks last (wait fctx)    -- gsync
__global__ void __launch_bounds__(NTHR) k_steps(const float* __restrict__ memory,
                                                const float* __restrict__ W_loc,
                                                const float* __restrict__ b_loc,
                                                const float* __restrict__ Wv,
                                                const int* __restrict__ mem_len,
                                                const float* __restrict__ W_lin,
                                                const float* __restrict__ b_lin,
                                                const float* __restrict__ W_gate,
                                                const float* __restrict__ b_gate,
                                                float* __restrict__ dout) {
    __shared__ __align__(16) float sh[5120];
    int bx = blockIdx.x;
    int ntile = bx & 31, s = bx >> 5;
    int n0 = ntile * 128;

    if (bx < 32) xcopy_phase(bx, 0);
    gsync();

    for (int t = 0; t < TDEC; t++) {
        unsigned ftarget = 32u * (unsigned)(t + 1);

        // ---- P_G1: GEMM-A (uniform splits of 448) ----
        {
            float acc[4][4] = {{0,0,0,0},{0,0,0,0},{0,0,0,0},{0,0,0,0}};
            gemm_chunks<KA>(g_cat_a, g_WaT, sh, s * 448, 0, 28, acc, n0);
            zp_store(g_zpA, acc, s, n0);
        }
        gsync();

        // ---- P_MID ----
        if (bx < 32)       combineA_phase(bx, sh);
        else if (bx < 64)  { if (t > 0) combineD_phase(bx - 32, W_lin, b_lin, W_gate, b_gate, dout, t - 1, sh); }
        else if (bx < 96)  { if (t + 1 < TDEC) xcopy_phase(bx - 64, t + 1); }
        __syncthreads();
        att1_phase(W_loc, b_loc, Wv, mem_len, ftarget, sh);
        gsync();

        // ---- P_G2: att2 + GEMM-D (splits 34/42/42/42, ctx chunks last) ----
        {
            if (s == 0) att2_phase(memory, dout, t, sh);
            float acc[4][4] = {{0,0,0,0},{0,0,0,0},{0,0,0,0},{0,0,0,0}};
            int k0, preA, preB, postA, postB;
            if (s == 0)      { k0 = 0;    preA = 0;  preB = 34; postA = 0;  postB = 0;  }
            else if (s == 1) { k0 = 544;  preA = 0;  preB = 30; postA = 30; postB = 42; }
            else if (s == 2) { k0 = 1216; preA = 20; preB = 42; postA = 0;  postB = 20; }
            else             { k0 = 1888; preA = 0;  preB = 42; postA = 0;  postB = 0;  }
            gemm_chunks<KD>(g_cat_d, g_WdT, sh, k0, preA, preB, acc, n0);
            if (postB > postA) {
                flag_wait(&g_fctx, ftarget);
                gemm_chunks<KD>(g_cat_d, g_WdT, sh, k0, postA, postB, acc, n0);
            }
            zp_store(g_zpD, acc, s, n0);
        }
        gsync();
    }
    if (bx >= 32 && bx < 64)
        combineD_phase(bx - 32, W_lin, b_lin, W_gate, b_gate, dout, TDEC - 1, sh);
}

// ---------------- host ----------------
extern "C" void kernel_launch(void* const* d_in, const int* in_sizes, int n_in,
                              void* d_out, int out_size) {
    const float* memory   = (const float*)d_in[0];
    const float* mel_tgt  = (const float*)d_in[1];
    const int*   mem_len  = (const int*)  d_in[2];
    const float* W_p1     = (const float*)d_in[3];
    const float* b_p1     = (const float*)d_in[4];
    const float* W_p2     = (const float*)d_in[5];
    const float* b_p2     = (const float*)d_in[6];
    const float* Wih_a    = (const float*)d_in[7];
    const float* Whh_a    = (const float*)d_in[8];
    const float* bih_a    = (const float*)d_in[9];
    const float* bhh_a    = (const float*)d_in[10];
    const float* Wq       = (const float*)d_in[11];
    const float* Wm       = (const float*)d_in[12];
    const float* Wv       = (const float*)d_in[13];
    const float* W_loc    = (const float*)d_in[14];
    const float* b_loc    = (const float*)d_in[15];
    const float* W_locd   = (const float*)d_in[16];
    const float* Wih_d    = (const float*)d_in[17];
    const float* Whh_d    = (const float*)d_in[18];
    const float* bih_d    = (const float*)d_in[19];
    const float* bhh_d    = (const float*)d_in[20];
    const float* W_lin    = (const float*)d_in[21];
    const float* b_lin    = (const float*)d_in[22];
    const float* W_gate   = (const float*)d_in[23];
    const float* b_gate   = (const float*)d_in[24];
    float* out = (float*)d_out;

    float *WaT, *WdT;
    cudaGetSymbolAddress((void**)&WaT, g_WaT);
    cudaGetSymbolAddress((void**)&WdT, g_WdT);

    // exactly 5 setup launches so ncu (-s 5 -c 1) profiles k_steps
    k_setup<<<512, 256>>>(bih_a, bhh_a, bih_d, bhh_d, Wq, Wm, W_p1, W_p2, W_locd);
    dim3 tb(32, 32);
    k_concatT<<<dim3(KA / 32, R4 / 32), tb>>>(WaT, Wih_a, Whh_a, 768, 1024, R4);
    k_concatT<<<dim3(KD / 32, R4 / 32), tb>>>(WdT, Wih_d, Whh_d, 1536, 1024, R4);
    k_keys<<<dim3(32, 16), 128>>>(memory);
    k_prenet<<<512, 256>>>(mel_tgt, b_p1, b_p2);

    k_steps<<<NBLK, NTHR>>>(memory, W_loc, b_loc, Wv, mem_len,
                            W_lin, b_lin, W_gate, b_gate, out);
}

// round 14
// speedup vs baseline: 1.6287x; 1.0649x over previous
#include <cuda_runtime.h>
#include <math.h>

// ---------------- problem constants ----------------
#define B32    32
#define TENC   256
#define TDEC   512
#define NMELS  80
#define EDIM   512
#define PRE    256
#define HID    1024
#define ATT    128
#define LOCF   32
#define LOCK   31
#define KA     1792           // PRE + EDIM + HID  (x | ctx | ah)
#define KD     2560           // HID + EDIM + HID  (ah | ctx | dh)
#define R4     4096
#define NSPL   8
#define NBLK   128
#define NTHR   256

#define MEL_SZ    (B32*NMELS*TDEC)
#define GATE_OFF  MEL_SZ
#define ALIGN_OFF (MEL_SZ + B32*TDEC)

// ---------------- static device buffers ----------------
__device__ float g_WaT[KA*R4];        // [k][r]
__device__ float g_WdT[KD*R4];        // [k][r]
__device__ float g_keys[B32*TENC*ATT];
__device__ float g_X[TDEC*B32*PRE];   // precomputed prenet outputs
__device__ float g_zpA[NSPL*B32*R4];  // split-K partials (attention LSTM)
__device__ float g_zpD[NSPL*B32*R4];  // split-K partials (decoder LSTM)
__device__ float g_Wqt[HID*ATT];
__device__ float g_Wmt[EDIM*ATT];
__device__ float g_Wp1t[NMELS*PRE];
__device__ float g_Wp2t[PRE*PRE];
__device__ float g_Wldt[LOCF*ATT];
__device__ float g_ba[R4];
__device__ float g_bd[R4];
__device__ float g_cat_a[B32*KA];     // [x | ctx | ah]
__device__ float g_cat_d[B32*KD];     // [ah | ctx | dh]
__device__ float g_ac[B32*HID];
__device__ float g_dc[B32*HID];
__device__ float g_aw[B32*TENC];
__device__ float g_awc[B32*TENC];
__device__ float g_q[B32*ATT];
__device__ float g_e[B32*TENC];

// sync state
__device__ unsigned g_barcnt = 0;
__device__ volatile unsigned g_epoch = 0;
__device__ unsigned g_fq = 0;
__device__ unsigned g_fctx = 0;

__device__ __forceinline__ float sigm(float x) { return 1.0f / (1.0f + expf(-x)); }
__device__ __forceinline__ unsigned rotl(unsigned x, int d) { return (x << d) | (x >> (32 - d)); }

__device__ __forceinline__ void gsync() {
    __syncthreads();
    if (threadIdx.x == 0) {
        __threadfence();
        unsigned e = g_epoch;
        if (atomicAdd(&g_barcnt, 1u) == NBLK - 1u) {
            g_barcnt = 0u;
            __threadfence();
            g_epoch = e + 1u;
        } else {
            while (g_epoch == e) { }
        }
        __threadfence();
    }
    __syncthreads();
}

__device__ __forceinline__ void flag_wait(unsigned* flag, unsigned target) {
    if (threadIdx.x == 0) {
        while (*(volatile unsigned*)flag < target) { }
        __threadfence();
    }
    __syncthreads();
}

// Bit-exact jax.random.bernoulli(jax.random.key(42), 0.5, (512,2,32,256)) * 2.0
// (jax_threefry_partitionable=True): per flat element i, threefry2x32 with key
// (0,42) on count pair (0, i); random word = out_x0 XOR out_x1; keep if top bit clear.
__device__ float drop_mask(unsigned idx) {
    unsigned x0 = 0u, x1 = idx;
    const unsigned ks0 = 0u, ks1 = 42u, ks2 = 0x1BD11BDAu ^ 42u;
    x0 += ks0; x1 += ks1;
#define RND(r) { x0 += x1; x1 = rotl(x1, r); x1 ^= x0; }
    RND(13) RND(15) RND(26) RND(6)  x0 += ks1; x1 += ks2 + 1u;
    RND(17) RND(29) RND(16) RND(24) x0 += ks2; x1 += ks0 + 2u;
    RND(13) RND(15) RND(26) RND(6)  x0 += ks0; x1 += ks1 + 3u;
    RND(17) RND(29) RND(16) RND(24) x0 += ks1; x1 += ks2 + 4u;
    RND(13) RND(15) RND(26) RND(6)  x0 += ks2; x1 += ks0 + 5u;
#undef RND
    unsigned bits = x0 ^ x1;
    return (bits & 0x80000000u) ? 0.0f : 2.0f;
}

// ---------------- setup helpers (run inside k_steps preamble) ----------------

// tiled transpose-concat: out[k][r] = (k<K1 ? in1[r][k] : in2[r][k-K1]); K,R mult of 32
__device__ void transpose_concat(float* __restrict__ out, const float* __restrict__ in1,
                                 const float* __restrict__ in2, int K1, int K2, int R,
                                 float* __restrict__ sh) {
    int K = K1 + K2;
    int ntx = K >> 5, nty = R >> 5;
    int total = ntx * nty;
    int t = threadIdx.x;
    int tx = t & 31, ty8 = t >> 5;
    for (int tile = blockIdx.x; tile < total; tile += NBLK) {
        int bkx = (tile % ntx) << 5, bry = (tile / ntx) << 5;
        __syncthreads();
#pragma unroll
        for (int p = 0; p < 4; p++) {
            int r = bry + ty8 + p * 8, k = bkx + tx;
            float v = (k < K1) ? in1[(size_t)r * K1 + k] : in2[(size_t)r * K2 + (k - K1)];
            sh[(ty8 + p * 8) * 33 + tx] = v;
        }
        __syncthreads();
#pragma unroll
        for (int p = 0; p < 4; p++) {
            int ko = bkx + ty8 + p * 8, ro = bry + tx;
            out[(size_t)ko * R + ro] = sh[tx * 33 + ty8 + p * 8];
        }
    }
    __syncthreads();
}

// keys for unit u (b = u&31, tc = u>>5): keys[b][tc*16+tt][a]
__device__ void keys_unit(const float* __restrict__ memory, int u, float* __restrict__ sh) {
    int b = u & 31, tc = u >> 5;
    int t = threadIdx.x;
    __syncthreads();
    for (int i = t; i < 16 * EDIM; i += 256) {
        int tt = i >> 9, d = i & 511;
        sh[i] = memory[((size_t)(b * TENC + tc * 16 + tt)) * EDIM + d];
    }
    __syncthreads();
    int a = t & 127, r0 = (t >> 7) * 8;
    float acc[8];
#pragma unroll
    for (int j = 0; j < 8; j++) acc[j] = 0.f;
    for (int d4 = 0; d4 < EDIM / 4; d4++) {
        float w0 = g_Wmt[(d4 * 4 + 0) * ATT + a];
        float w1 = g_Wmt[(d4 * 4 + 1) * ATT + a];
        float w2 = g_Wmt[(d4 * 4 + 2) * ATT + a];
        float w3 = g_Wmt[(d4 * 4 + 3) * ATT + a];
#pragma unroll
        for (int tt = 0; tt < 8; tt++) {
            float4 m = *(const float4*)&sh[(r0 + tt) * EDIM + d4 * 4];
            acc[tt] += m.x * w0 + m.y * w1 + m.z * w2 + m.w * w3;
        }
    }
    for (int tt = 0; tt < 8; tt++)
        g_keys[((size_t)(b * TENC + tc * 16 + r0 + tt)) * ATT + a] = acc[tt];
    __syncthreads();
}

// prenet for step ts (teacher forcing + exact dropout); ts==0 also fills cat_a x-slot
__device__ void prenet_unit(const float* __restrict__ mel_target,
                            const float* __restrict__ b_p1,
                            const float* __restrict__ b_p2,
                            int ts, float* __restrict__ sh) {
    int j = threadIdx.x;
    float* sDec = sh;          // 2560
    float* sX1  = sh + 2560;   // 8192
    __syncthreads();
    for (int i = j; i < B32 * NMELS; i += 256) {
        int b = i / NMELS, m = i % NMELS;
        sDec[i] = (ts == 0) ? 0.f : mel_target[((size_t)(b * NMELS + m)) * TDEC + (ts - 1)];
    }
    __syncthreads();
    float acc[B32];
#pragma unroll
    for (int b = 0; b < B32; b++) acc[b] = 0.f;
    for (int m4 = 0; m4 < NMELS / 4; m4++) {
        float w0 = g_Wp1t[(4 * m4 + 0) * PRE + j];
        float w1 = g_Wp1t[(4 * m4 + 1) * PRE + j];
        float w2 = g_Wp1t[(4 * m4 + 2) * PRE + j];
        float w3 = g_Wp1t[(4 * m4 + 3) * PRE + j];
#pragma unroll
        for (int b = 0; b < B32; b++) {
            float4 d = *(const float4*)&sDec[b * NMELS + 4 * m4];
            acc[b] += d.x * w0 + d.y * w1 + d.z * w2 + d.w * w3;
        }
    }
    float bb = b_p1[j];
#pragma unroll
    for (int b = 0; b < B32; b++) {
        float v = acc[b] + bb; v = v > 0.f ? v : 0.f;
        v *= drop_mask(((unsigned)(ts * 2 + 0) * B32 + b) * PRE + j);
        sX1[b * PRE + j] = v;
    }
    __syncthreads();
#pragma unroll
    for (int b = 0; b < B32; b++) acc[b] = 0.f;
    for (int k4 = 0; k4 < PRE / 4; k4++) {
        float w0 = g_Wp2t[(4 * k4 + 0) * PRE + j];
        float w1 = g_Wp2t[(4 * k4 + 1) * PRE + j];
        float w2 = g_Wp2t[(4 * k4 + 2) * PRE + j];
        float w3 = g_Wp2t[(4 * k4 + 3) * PRE + j];
#pragma unroll
        for (int b = 0; b < B32; b++) {
            float4 x = *(const float4*)&sX1[b * PRE + 4 * k4];
            acc[b] += x.x * w0 + x.y * w1 + x.z * w2 + x.w * w3;
        }
    }
    bb = b_p2[j];
#pragma unroll
    for (int b = 0; b < B32; b++) {
        float v = acc[b] + bb; v = v > 0.f ? v : 0.f;
        v *= drop_mask(((unsigned)(ts * 2 + 1) * B32 + b) * PRE + j);
        g_X[((size_t)(ts * B32 + b)) * PRE + j] = v;
        if (ts == 0) g_cat_a[b * KA + j] = v;
    }
    __syncthreads();
}

// ---------------- main-loop phase bodies ----------------

// Double-buffered GEMM over absolute 16-k chunks [c0,c1); tile 32b x 256n, 4x8/thread.
// smem: As[2][512] at sh[0..1023], Ws[2][4096] at sh[1024..9215].
template <int K>
__device__ __forceinline__ void gemm_chunks(const float* __restrict__ A,
                                            const float* __restrict__ W,
                                            float* __restrict__ sh,
                                            int c0, int c1,
                                            float (&acc)[4][8], int n0) {
    int nc = c1 - c0;
    if (nc <= 0) return;
    int t = threadIdx.x;
    int lb = t >> 3, lk2 = (t & 7) * 2;
    int lkk = t >> 4, ln = (t & 15) * 16;
    int bq = (t & 7) * 4, nq = (t >> 3) * 8;
    float* As = sh;
    float* Ws = sh + 1024;
    float2 ra;
    float4 rw0, rw1, rw2, rw3;
    {
        int kb = c0 * 16;
        ra = *(const float2*)(A + (size_t)lb * K + kb + lk2);
        const float* wsrc = W + (size_t)(kb + lkk) * R4 + n0 + ln;
        rw0 = ((const float4*)wsrc)[0]; rw1 = ((const float4*)wsrc)[1];
        rw2 = ((const float4*)wsrc)[2]; rw3 = ((const float4*)wsrc)[3];
        As[lk2 * 32 + lb] = ra.x; As[(lk2 + 1) * 32 + lb] = ra.y;
        float4* wd = (float4*)&Ws[lkk * 256 + ln];
        wd[0] = rw0; wd[1] = rw1; wd[2] = rw2; wd[3] = rw3;
    }
    __syncthreads();
    for (int it = 0; it < nc; it++) {
        if (it + 1 < nc) {
            int kb = (c0 + it + 1) * 16;
            ra = *(const float2*)(A + (size_t)lb * K + kb + lk2);
            const float* wsrc = W + (size_t)(kb + lkk) * R4 + n0 + ln;
            rw0 = ((const float4*)wsrc)[0]; rw1 = ((const float4*)wsrc)[1];
            rw2 = ((const float4*)wsrc)[2]; rw3 = ((const float4*)wsrc)[3];
        }
        const float* Ab = As + (it & 1) * 512;
        const float* Wb = Ws + (it & 1) * 4096;
#pragma unroll
        for (int kk = 0; kk < 16; kk++) {
            float4 av = *(const float4*)&Ab[kk * 32 + bq];
            float4 w0 = *(const float4*)&Wb[kk * 256 + nq];
            float4 w1 = *(const float4*)&Wb[kk * 256 + nq + 4];
            acc[0][0] += av.x * w0.x; acc[0][1] += av.x * w0.y; acc[0][2] += av.x * w0.z; acc[0][3] += av.x * w0.w;
            acc[0][4] += av.x * w1.x; acc[0][5] += av.x * w1.y; acc[0][6] += av.x * w1.z; acc[0][7] += av.x * w1.w;
            acc[1][0] += av.y * w0.x; acc[1][1] += av.y * w0.y; acc[1][2] += av.y * w0.z; acc[1][3] += av.y * w0.w;
            acc[1][4] += av.y * w1.x; acc[1][5] += av.y * w1.y; acc[1][6] += av.y * w1.z; acc[1][7] += av.y * w1.w;
            acc[2][0] += av.z * w0.x; acc[2][1] += av.z * w0.y; acc[2][2] += av.z * w0.z; acc[2][3] += av.z * w0.w;
            acc[2][4] += av.z * w1.x; acc[2][5] += av.z * w1.y; acc[2][6] += av.z * w1.z; acc[2][7] += av.z * w1.w;
            acc[3][0] += av.w * w0.x; acc[3][1] += av.w * w0.y; acc[3][2] += av.w * w0.z; acc[3][3] += av.w * w0.w;
            acc[3][4] += av.w * w1.x; acc[3][5] += av.w * w1.y; acc[3][6] += av.w * w1.z; acc[3][7] += av.w * w1.w;
        }
        if (it + 1 < nc) {
            float* Abn = As + ((it + 1) & 1) * 512;
            float* Wbn = Ws + ((it + 1) & 1) * 4096;
            Abn[lk2 * 32 + lb] = ra.x; Abn[(lk2 + 1) * 32 + lb] = ra.y;
            float4* wd = (float4*)&Wbn[lkk * 256 + ln];
            wd[0] = rw0; wd[1] = rw1; wd[2] = rw2; wd[3] = rw3;
            __syncthreads();
        }
    }
    __syncthreads();
}

__device__ __forceinline__ void zp_store(float* __restrict__ zp, float (&acc)[4][8],
                                         int s, int n0) {
    int t = threadIdx.x;
    int bq = (t & 7) * 4, nq = (t >> 3) * 8;
#pragma unroll
    for (int i = 0; i < 4; i++) {
        float* dst = &zp[((size_t)(s * B32 + bq + i)) * R4 + n0 + nq];
        *(float4*)dst = make_float4(acc[i][0], acc[i][1], acc[i][2], acc[i][3]);
        *(float4*)(dst + 4) = make_float4(acc[i][4], acc[i][5], acc[i][6], acc[i][7]);
    }
}

// combineA: gates -> ah, ac; q = ah @ Wq.T; release g_fq
__device__ __forceinline__ void combineA_phase(int b, float* __restrict__ sh) {
    int t = threadIdx.x;
    float* sAh = sh;
    float* sQ = sh + 1024;
#pragma unroll
    for (int u = 0; u < 4; u++) {
        int h = u * 256 + t;
        float zi = g_ba[h], zf = g_ba[HID + h], zg = g_ba[2 * HID + h], zo = g_ba[3 * HID + h];
#pragma unroll
        for (int sp = 0; sp < NSPL; sp++) {
            const float* zp = &g_zpA[((size_t)(sp * B32 + b)) * R4];
            zi += zp[h]; zf += zp[HID + h]; zg += zp[2 * HID + h]; zo += zp[3 * HID + h];
        }
        float c = sigm(zf) * g_ac[b * HID + h] + sigm(zi) * tanhf(zg);
        float hn = sigm(zo) * tanhf(c);
        g_ac[b * HID + h] = c;
        sAh[h] = hn;
        g_cat_a[b * KA + 768 + h] = hn;
        g_cat_d[b * KD + h] = hn;
    }
    __syncthreads();
    int a = t & 127, half = t >> 7;
    int j0 = half * 512;
    float a0 = 0.f, a1 = 0.f, a2 = 0.f, a3 = 0.f;
    for (int j = 0; j < 512; j += 4) {
        a0 += sAh[j0 + j]     * g_Wqt[(j0 + j) * ATT + a];
        a1 += sAh[j0 + j + 1] * g_Wqt[(j0 + j + 1) * ATT + a];
        a2 += sAh[j0 + j + 2] * g_Wqt[(j0 + j + 2) * ATT + a];
        a3 += sAh[j0 + j + 3] * g_Wqt[(j0 + j + 3) * ATT + a];
    }
    sQ[half * ATT + a] = (a0 + a1) + (a2 + a3);
    __syncthreads();
    if (t < ATT) g_q[b * ATT + t] = sQ[t] + sQ[ATT + t];
    __syncthreads();
    if (t == 0) { __threadfence(); atomicAdd(&g_fq, 1u); }
}

// att1: conv (t-1 state) -> wait q flag -> energies for a 64-t chunk
__device__ __forceinline__ void att1_phase(const float* __restrict__ W_loc,
                                           const float* __restrict__ b_loc,
                                           const float* __restrict__ Wv,
                                           const int* __restrict__ mem_len,
                                           unsigned fq_target,
                                           float* __restrict__ sh) {
    int bx = blockIdx.x;
    int b = bx & 31, tc = bx >> 5;
    int t = threadIdx.x;
    int tbase = tc * 64;
    float* sAw0 = sh;
    float* sAw1 = sh + 96;
    float* sQ   = sh + 192;
    float* sWl  = sh + 320;
    float* sLoc = sh + 2304;
    float* sEp  = sh + 4352;
    for (int i = t; i < 94; i += 256) {
        int tt = tbase - 15 + i;
        bool ok = (tt >= 0) && (tt < TENC);
        sAw0[i] = ok ? g_aw[b * TENC + tt] : 0.f;
        sAw1[i] = ok ? g_awc[b * TENC + tt] : 0.f;
    }
    for (int i = t; i < LOCF * 2 * LOCK; i += 256) sWl[i] = W_loc[i];
    __syncthreads();
    for (int i = t; i < 64 * LOCF; i += 256) {
        int f = i & 31, tt = i >> 5;
        const float* w0 = &sWl[f * 62];
        const float* w1 = &sWl[f * 62 + 31];
        float c0 = b_loc[f], c1 = 0.f, c2 = 0.f, c3 = 0.f;
#pragma unroll
        for (int k = 0; k < 30; k += 2) {
            c0 += sAw0[tt + k] * w0[k];
            c1 += sAw0[tt + k + 1] * w0[k + 1];
            c2 += sAw1[tt + k] * w1[k];
            c3 += sAw1[tt + k + 1] * w1[k + 1];
        }
        c0 += sAw0[tt + 30] * w0[30];
        c2 += sAw1[tt + 30] * w1[30];
        sLoc[tt * 32 + f] = (c0 + c1) + (c2 + c3);
    }
    flag_wait(&g_fq, fq_target);
    if (t < ATT) sQ[t] = g_q[b * ATT + t];
    __syncthreads();
    int a = t & 127;
    int half = t >> 7;
    float wld[32];
#pragma unroll
    for (int f = 0; f < 32; f++) wld[f] = g_Wldt[f * ATT + a];
    float wv = Wv[a];
    float qa = sQ[a];
    int lane = t & 31, w = t >> 5;
#pragma unroll 2
    for (int tl = 0; tl < 32; tl++) {
        int tt = half * 32 + tl;
        float l0 = 0.f, l1 = 0.f, l2 = 0.f, l3 = 0.f;
#pragma unroll
        for (int f = 0; f < 8; f++) {
            l0 += sLoc[tt * 32 + f]      * wld[f];
            l1 += sLoc[tt * 32 + f + 8]  * wld[f + 8];
            l2 += sLoc[tt * 32 + f + 16] * wld[f + 16];
            l3 += sLoc[tt * 32 + f + 24] * wld[f + 24];
        }
        float lA = (l0 + l1) + (l2 + l3);
        float v = tanhf(qa + g_keys[((size_t)(b * TENC + tbase + tt)) * ATT + a] + lA) * wv;
        for (int off = 16; off; off >>= 1) v += __shfl_down_sync(0xffffffffu, v, off);
        if (lane == 0) sEp[w * 32 + tl] = v;
    }
    __syncthreads();
    int L = mem_len[b];
    for (int tt = t; tt < 64; tt += 256) {
        float e;
        if (tt < 32) e = sEp[tt] + sEp[32 + tt] + sEp[64 + tt] + sEp[96 + tt];
        else { int tl = tt - 32; e = sEp[128 + tl] + sEp[160 + tl] + sEp[192 + tl] + sEp[224 + tl]; }
        int tg = tbase + tt;
        g_e[b * TENC + tg] = (tg >= L) ? -1e30f : e;
    }
}

// att2: softmax -> aw, awc, alignments, ctx; release g_fctx
__device__ __forceinline__ void att2_phase(const float* __restrict__ memory, int b,
                                           float* __restrict__ dout, int tstep,
                                           float* __restrict__ sh) {
    int t = threadIdx.x;
    float* sE = sh;
    float* sR1 = sh + 256;
    float* sR2 = sh + 264;
    sE[t] = g_e[b * TENC + t];
    __syncthreads();
    float v = sE[t];
    for (int off = 16; off; off >>= 1) v = fmaxf(v, __shfl_down_sync(0xffffffffu, v, off));
    if ((t & 31) == 0) sR1[t >> 5] = v;
    __syncthreads();
    if (t < 8) {
        float m = sR1[t];
        for (int off = 4; off; off >>= 1) m = fmaxf(m, __shfl_down_sync(0xffu, m, off));
        if (t == 0) sR1[0] = m;
    }
    __syncthreads();
    float mx = sR1[0];
    float p = expf(sE[t] - mx);
    float sv = p;
    for (int off = 16; off; off >>= 1) sv += __shfl_down_sync(0xffffffffu, sv, off);
    if ((t & 31) == 0) sR2[t >> 5] = sv;
    __syncthreads();
    if (t < 8) {
        float m = sR2[t];
        for (int off = 4; off; off >>= 1) m += __shfl_down_sync(0xffu, m, off);
        if (t == 0) sR2[0] = m;
    }
    __syncthreads();
    float aw = p / sR2[0];
    __syncthreads();
    sE[t] = aw;
    g_aw[b * TENC + t] = aw;
    g_awc[b * TENC + t] += aw;
    dout[ALIGN_OFF + ((size_t)(b * TDEC + tstep)) * TENC + t] = aw;
    __syncthreads();
    int d = t;
    float p00 = 0.f, p01 = 0.f, p02 = 0.f, p03 = 0.f;
    float p10 = 0.f, p11 = 0.f, p12 = 0.f, p13 = 0.f;
    for (int tt = 0; tt < TENC; tt += 4) {
        const float* m0 = &memory[((size_t)(b * TENC + tt)) * EDIM];
        float a0 = sE[tt], a1 = sE[tt + 1], a2 = sE[tt + 2], a3 = sE[tt + 3];
        p00 += a0 * m0[d];               p10 += a0 * m0[d + 256];
        p01 += a1 * m0[EDIM + d];        p11 += a1 * m0[EDIM + d + 256];
        p02 += a2 * m0[2 * EDIM + d];    p12 += a2 * m0[2 * EDIM + d + 256];
        p03 += a3 * m0[3 * EDIM + d];    p13 += a3 * m0[3 * EDIM + d + 256];
    }
    float acc0 = (p00 + p01) + (p02 + p03);
    float acc1 = (p10 + p11) + (p12 + p13);
    g_cat_a[b * KA + 256 + d] = acc0;
    g_cat_a[b * KA + 256 + d + 256] = acc1;
    g_cat_d[b * KD + HID + d] = acc0;
    g_cat_d[b * KD + HID + d + 256] = acc1;
    __syncthreads();
    if (t == 0) { __threadfence(); atomicAdd(&g_fctx, 1u); }
    __syncthreads();
}

// combineD: gates -> dh, dc; mel/gate projections
__device__ __forceinline__ void combineD_phase(int b,
                                               const float* __restrict__ W_lin,
                                               const float* __restrict__ b_lin,
                                               const float* __restrict__ W_gate,
                                               const float* __restrict__ b_gate,
                                               float* __restrict__ dout, int tstep,
                                               float* __restrict__ sh) {
    int t = threadIdx.x;
    float* sOut = sh;
#pragma unroll
    for (int u = 0; u < 4; u++) {
        int h = u * 256 + t;
        float zi = g_bd[h], zf = g_bd[HID + h], zg = g_bd[2 * HID + h], zo = g_bd[3 * HID + h];
#pragma unroll
        for (int sp = 0; sp < NSPL; sp++) {
            const float* zp = &g_zpD[((size_t)(sp * B32 + b)) * R4];
            zi += zp[h]; zf += zp[HID + h]; zg += zp[2 * HID + h]; zo += zp[3 * HID + h];
        }
        float c = sigm(zf) * g_dc[b * HID + h] + sigm(zi) * tanhf(zg);
        float hn = sigm(zo) * tanhf(c);
        g_dc[b * HID + h] = c;
        g_cat_d[b * KD + 1536 + h] = hn;
        sOut[h] = hn;
    }
    for (int i = t; i < EDIM; i += 256) sOut[HID + i] = g_cat_d[b * KD + HID + i];
    __syncthreads();
    int lane = t & 31, w = t >> 5;
    for (int m = w; m < 81; m += 8) {
        const float* row; float bias;
        if (m < 80) { row = W_lin + (size_t)m * 1536; bias = b_lin[m]; }
        else        { row = W_gate; bias = b_gate[0]; }
        float a0 = 0.f, a1 = 0.f, a2 = 0.f, a3 = 0.f;
        for (int k = lane; k < 1536; k += 128) {
            a0 += sOut[k] * row[k];
            a1 += sOut[k + 32] * row[k + 32];
            a2 += sOut[k + 64] * row[k + 64];
            a3 += sOut[k + 96] * row[k + 96];
        }
        float acc = (a0 + a1) + (a2 + a3);
        for (int off = 16; off; off >>= 1) acc += __shfl_down_sync(0xffffffffu, acc, off);
        if (lane == 0) {
            float r = acc + bias;
            if (m < 80) dout[((size_t)(b * NMELS + m)) * TDEC + tstep] = r;
            else        dout[GATE_OFF + b * TDEC + tstep] = r;
        }
    }
}

__device__ __forceinline__ void xcopy_phase(int b, int tstep) {
    int t = threadIdx.x;
    g_cat_a[b * KA + t] = g_X[((size_t)(tstep * B32 + b)) * PRE + t];
}

// ---------------- the single persistent kernel ----------------
__global__ void __launch_bounds__(NTHR) k_steps(
    const float* __restrict__ memory, const float* __restrict__ mel_target,
    const int* __restrict__ mem_len,
    const float* __restrict__ W_p1, const float* __restrict__ b_p1,
    const float* __restrict__ W_p2, const float* __restrict__ b_p2,
    const float* __restrict__ Wih_a, const float* __restrict__ Whh_a,
    const float* __restrict__ bih_a, const float* __restrict__ bhh_a,
    const float* __restrict__ Wq, const float* __restrict__ Wm,
    const float* __restrict__ Wv, const float* __restrict__ W_loc,
    const float* __restrict__ b_loc, const float* __restrict__ W_locd,
    const float* __restrict__ Wih_d, const float* __restrict__ Whh_d,
    const float* __restrict__ bih_d, const float* __restrict__ bhh_d,
    const float* __restrict__ W_lin, const float* __restrict__ b_lin,
    const float* __restrict__ W_gate, const float* __restrict__ b_gate,
    float* __restrict__ dout) {
    __shared__ __align__(16) float sh[10752];
    int bx = blockIdx.x;

    // ---- setup S1: state init + small transposes (grid-strided) ----
    {
        int gtid = bx * NTHR + threadIdx.x;
        const int GN = NBLK * NTHR;
        for (int i = gtid; i < B32*KA;   i += GN) g_cat_a[i] = 0.f;
        for (int i = gtid; i < B32*KD;   i += GN) g_cat_d[i] = 0.f;
        for (int i = gtid; i < B32*HID;  i += GN) { g_ac[i] = 0.f; g_dc[i] = 0.f; }
        for (int i = gtid; i < B32*TENC; i += GN) { g_aw[i] = 0.f; g_awc[i] = 0.f; }
        for (int i = gtid; i < R4;       i += GN) { g_ba[i] = bih_a[i] + bhh_a[i]; g_bd[i] = bih_d[i] + bhh_d[i]; }
        for (int i = gtid; i < HID*ATT;  i += GN) { int k = i >> 7, a = i & 127; g_Wqt[i]  = Wq[a*HID + k]; }
        for (int i = gtid; i < EDIM*ATT; i += GN) { int k = i >> 7, a = i & 127; g_Wmt[i]  = Wm[a*EDIM + k]; }
        for (int i = gtid; i < NMELS*PRE;i += GN) { int m = i >> 8, j = i & 255; g_Wp1t[i] = W_p1[j*NMELS + m]; }
        for (int i = gtid; i < PRE*PRE;  i += GN) { int k = i >> 8, j = i & 255; g_Wp2t[i] = W_p2[j*PRE + k]; }
        for (int i = gtid; i < LOCF*ATT; i += GN) { int f = i >> 7, a = i & 127; g_Wldt[i] = W_locd[a*LOCF + f]; }
        if (gtid == 0) { g_fq = 0u; g_fctx = 0u; }
    }
    gsync();
    // ---- setup S2: big transposes + keys + prenet ----
    transpose_concat(g_WaT, Wih_a, Whh_a, 768, 1024, R4, sh);
    transpose_concat(g_WdT, Wih_d, Whh_d, 1536, 1024, R4, sh);
    for (int u = bx; u < 512; u += NBLK) keys_unit(memory, u, sh);
    for (int ts = bx; ts < TDEC; ts += NBLK) prenet_unit(mel_target, b_p1, b_p2, ts, sh);
    gsync();

    // ---- main loop ----
    int ntile = bx & 15, s = bx >> 4;
    int n0 = ntile * 256;
    int pA0, pA1, pB0, pB1;
    switch (s) {
        case 0:  pA0 = 0;   pA1 = 14;  pB0 = 0;  pB1 = 0;  break;
        case 1:  pA0 = 14;  pA1 = 28;  pB0 = 0;  pB1 = 0;  break;
        case 2:  pA0 = 28;  pA1 = 46;  pB0 = 64; pB1 = 68; break;
        case 3:  pA0 = 46;  pA1 = 64;  pB0 = 68; pB1 = 72; break;
        case 4:  pA0 = 96;  pA1 = 114; pB0 = 72; pB1 = 76; break;
        case 5:  pA0 = 114; pA1 = 132; pB0 = 76; pB1 = 80; break;
        case 6:  pA0 = 132; pA1 = 146; pB0 = 80; pB1 = 88; break;
        default: pA0 = 146; pA1 = 160; pB0 = 88; pB1 = 96; break;
    }

    for (int t = 0; t < TDEC; t++) {
        unsigned ftarget = 32u * (unsigned)(t + 1);

        // P_G1: GEMM-A, 8 uniform splits of 14 chunks
        {
            float acc[4][8];
#pragma unroll
            for (int i = 0; i < 4; i++)
#pragma unroll
                for (int j = 0; j < 8; j++) acc[i][j] = 0.f;
            gemm_chunks<KA>(g_cat_a, g_WaT, sh, s * 14, s * 14 + 14, acc, n0);
            zp_store(g_zpA, acc, s, n0);
        }
        gsync();

        // P_MID
        if (bx < 32)       combineA_phase(bx, sh);
        else if (bx < 64)  { if (t > 0) combineD_phase(bx - 32, W_lin, b_lin, W_gate, b_gate, dout, t - 1, sh); }
        else if (bx < 96)  { if (t + 1 < TDEC) xcopy_phase(bx - 64, t + 1); }
        __syncthreads();
        att1_phase(W_loc, b_loc, Wv, mem_len, ftarget, sh);
        gsync();

        // P_G2: att2 (blocks 0-31) + GEMM-D (ctx chunks gated on fctx)
        {
            if (bx < 32) att2_phase(memory, bx, dout, t, sh);
            float acc[4][8];
#pragma unroll
            for (int i = 0; i < 4; i++)
#pragma unroll
                for (int j = 0; j < 8; j++) acc[i][j] = 0.f;
            gemm_chunks<KD>(g_cat_d, g_WdT, sh, pA0, pA1, acc, n0);
            if (pB1 > pB0) {
                flag_wait(&g_fctx, ftarget);
                gemm_chunks<KD>(g_cat_d, g_WdT, sh, pB0, pB1, acc, n0);
            }
            zp_store(g_zpD, acc, s, n0);
        }
        gsync();
    }
    if (bx >= 32 && bx < 64)
        combineD_phase(bx - 32, W_lin, b_lin, W_gate, b_gate, dout, TDEC - 1, sh);
}

// ---------------- host ----------------
extern "C" void kernel_launch(void* const* d_in, const int* in_sizes, int n_in,
                              void* d_out, int out_size) {
    const float* memory   = (const float*)d_in[0];
    const float* mel_tgt  = (const float*)d_in[1];
    const int*   mem_len  = (const int*)  d_in[2];
    const float* W_p1     = (const float*)d_in[3];
    const float* b_p1     = (const float*)d_in[4];
    const float* W_p2     = (const float*)d_in[5];
    const float* b_p2     = (const float*)d_in[6];
    const float* Wih_a    = (const float*)d_in[7];
    const float* Whh_a    = (const float*)d_in[8];
    const float* bih_a    = (const float*)d_in[9];
    const float* bhh_a    = (const float*)d_in[10];
    const float* Wq       = (const float*)d_in[11];
    const float* Wm       = (const float*)d_in[12];
    const float* Wv       = (const float*)d_in[13];
    const float* W_loc    = (const float*)d_in[14];
    const float* b_loc    = (const float*)d_in[15];
    const float* W_locd   = (const float*)d_in[16];
    const float* Wih_d    = (const float*)d_in[17];
    const float* Whh_d    = (const float*)d_in[18];
    const float* bih_d    = (const float*)d_in[19];
    const float* bhh_d    = (const float*)d_in[20];
    const float* W_lin    = (const float*)d_in[21];
    const float* b_lin    = (const float*)d_in[22];
    const float* W_gate   = (const float*)d_in[23];
    const float* b_gate   = (const float*)d_in[24];
    float* out = (float*)d_out;

    k_steps<<<NBLK, NTHR>>>(memory, mel_tgt, mem_len,
                            W_p1, b_p1, W_p2, b_p2,
                            Wih_a, Whh_a, bih_a, bhh_a,
                            Wq, Wm, Wv, W_loc, b_loc, W_locd,
                            Wih_d, Whh_d, bih_d, bhh_d,
                            W_lin, b_lin, W_gate, b_gate, out);
}